// round 14
// baseline (speedup 1.0000x reference)
#include <cuda_runtime.h>

#define N_SAMP 384
#define M 12
#define NP 6
#define UC (M * NP)      // 72 complex entries per sample
#define NBLK 576         // 24 x 24 pair tiles
#define NBUILD 256       // builder tickets; 3 samples each = 768

typedef unsigned long long u64;

// Duplicated packed operand formats (built in-kernel by ticket holders):
// g_u1d entry e=(k*6+b): [2e]=(re,im)=bp  [2e+1]=(-im,re)=bn
// g_u2d entry e=(k*6+a): [2e]=(cre,cre)=aR [2e+1]=(cim,cim)=aI  (c = conj(U2))
__device__ __align__(16) float2 g_u1d[N_SAMP * UC * 2];
__device__ __align__(16) float2 g_u2d[N_SAMP * UC * 2];

// handshake state; self-resetting across graph replays
__device__ unsigned g_ticket = 0;
__device__ unsigned g_cnt    = 0;
__device__ unsigned g_done   = 0;

__device__ __forceinline__ float2 cmul(float2 a, float2 b) {
    return make_float2(a.x * b.x - a.y * b.y, a.x * b.y + a.y * b.x);
}

// ---- packed f32x2 helpers ----
__device__ __forceinline__ float2 upk(u64 d) {
    float2 r; asm("mov.b64 {%0,%1}, %2;" : "=f"(r.x), "=f"(r.y) : "l"(d)); return r;
}
__device__ __forceinline__ u64 ffma2(u64 a, u64 b, u64 c) {
    u64 d; asm("fma.rn.f32x2 %0, %1, %2, %3;" : "=l"(d) : "l"(a), "l"(b), "l"(c)); return d;
}
__device__ __forceinline__ u64 fmul2(u64 a, u64 b) {
    u64 d; asm("mul.rn.f32x2 %0, %1, %2;" : "=l"(d) : "l"(a), "l"(b)); return d;
}
__device__ __forceinline__ u64 fadd2(u64 a, u64 b) {
    u64 d; asm("add.rn.f32x2 %0, %1, %2;" : "=l"(d) : "l"(a), "l"(b)); return d;
}

#define SPV 73   // smem pitch in ulonglong2 (16B units, odd -> conflict-free)

__device__ __forceinline__ float2 prod6f(const float2* r) {
    float2 p01 = cmul(r[0], r[1]);
    float2 p23 = cmul(r[2], r[3]);
    float2 p45 = cmul(r[4], r[5]);
    return cmul(cmul(p01, p23), p45);
}

__global__ __launch_bounds__(256, 2) void fused_kernel(
    const float* __restrict__ x1, const float* __restrict__ x2,
    const float* __restrict__ A_re, const float* __restrict__ A_im,
    const float* __restrict__ B_re, const float* __restrict__ B_im,
    float* __restrict__ out)
{
    __shared__ __align__(16) ulonglong2 s1[16 * SPV];
    __shared__ __align__(16) ulonglong2 s2[16 * SPV];
    __shared__ unsigned sticket;

    const int tid = threadIdx.x;
    const int bid = blockIdx.y * 24 + blockIdx.x;

    // ---------------- ticket claim -------------------------------------------
    if (tid == 0) sticket = atomicAdd(&g_ticket, 1u);
    __syncthreads();
    const unsigned tk = sticket;

    // ---------------- build phase: first NBUILD arrivals, 3 samples each ------
    if (tk < NBUILD) {
        // overlay scratch on s1 (overwritten after the global barrier)
        float2* ph = (float2*)s1;        // [3][12] phases
        float2* sA = ph + 3 * M;         // [12][12]
        float2* sB = sA + M * M;         // [12][6]

        for (int i = tid; i < M * M; i += 256)
            sA[i] = make_float2(A_re[i], A_im[i]);
        for (int i = tid; i < M * NP; i += 256) {
            int b = i / NP, c = i - b * NP;
            sB[i] = make_float2(B_re[b * M + c], B_im[b * M + c]);
        }
        if (tid < 3 * M) {
            int si = tid / M, m = tid - si * M;
            int s  = (int)tk * 3 + si;                    // 0..767
            float xv = (s < N_SAMP) ? x1[s * M + m] : x2[(s - N_SAMP) * M + m];
            float sn, cs;
            sincosf(xv, &sn, &cs);
            ph[tid] = make_float2(cs, sn);
        }
        __syncthreads();

        if (tid < 3 * UC) {
            int si = tid / UC, t = tid - si * UC;
            int a = t / NP, c = t - a * NP;
            int s = (int)tk * 3 + si;
            float2 acc = make_float2(0.f, 0.f);
#pragma unroll
            for (int b = 0; b < M; ++b) {
                float2 tp = cmul(ph[si * M + b], sB[b * NP + c]);
                float2 Av = sA[a * M + b];
                acc.x += Av.x * tp.x - Av.y * tp.y;
                acc.y += Av.x * tp.y + Av.y * tp.x;
            }
            if (s < N_SAMP) {
                int base = (s * UC + t) * 2;
                g_u1d[base + 0] = make_float2(acc.x, acc.y);    // bp
                g_u1d[base + 1] = make_float2(-acc.y, acc.x);   // bn
            } else {
                int base = ((s - N_SAMP) * UC + t) * 2;
                g_u2d[base + 0] = make_float2(acc.x, acc.x);    // aR (conj re)
                g_u2d[base + 1] = make_float2(-acc.y, -acc.y);  // aI (conj im)
            }
        }
        __threadfence();
        __syncthreads();
        if (tid == 0) atomicAdd(&g_cnt, 1u);
    }

    // ---------------- global barrier: all NBUILD builds visible ---------------
    if (tid == 0) {
        while (*(volatile unsigned*)&g_cnt < (unsigned)NBUILD) __nanosleep(64);
    }
    __syncthreads();
    __threadfence();

    // ---------------- pair phase (identical to R12 best) ----------------------
    const int i0 = blockIdx.y * 16;
    const int j0 = blockIdx.x * 16;

    const ulonglong2* __restrict__ gu1 = (const ulonglong2*)g_u1d;
    const ulonglong2* __restrict__ gu2 = (const ulonglong2*)g_u2d;
    for (int e = tid; e < 16 * UC; e += 256) {
        int l = e / UC;
        int r = e - l * UC;
        s1[l * SPV + r] = gu1[(i0 + l) * UC + r];
        s2[l * SPV + r] = gu2[(j0 + l) * UC + r];
    }
    __syncthreads();

    const int lj = tid & 15;        // j fastest -> coalesced output
    const int li = tid >> 4;
    const ulonglong2* __restrict__ p1 = &s1[li * SPV];   // {bp, bn}
    const ulonglong2* __restrict__ p2 = &s2[lj * SPV];   // {aR, aI}

    u64 W[NP][NP];

    // k = 0 initializes W
    {
        ulonglong2 bb[NP];
#pragma unroll
        for (int b = 0; b < NP; ++b) bb[b] = p1[b];
#pragma unroll
        for (int a = 0; a < NP; ++a) {
            const ulonglong2 av = p2[a];
#pragma unroll
            for (int b = 0; b < NP; ++b)
                W[a][b] = ffma2(av.y, bb[b].y, fmul2(av.x, bb[b].x));
        }
    }

#pragma unroll
    for (int k = 1; k < M; ++k) {
        ulonglong2 bb[NP];
#pragma unroll
        for (int b = 0; b < NP; ++b) bb[b] = p1[k * NP + b];
#pragma unroll
        for (int a = 0; a < NP; ++a) {
            const ulonglong2 av = p2[k * NP + a];
#pragma unroll
            for (int b = 0; b < NP; ++b) {
                W[a][b] = ffma2(av.x, bb[b].x, W[a][b]);
                W[a][b] = ffma2(av.y, bb[b].y, W[a][b]);
            }
        }
    }

    // --- Glynn permanent, n=6, single Gray chain, FFMA-imm updates ---
    float2 r[NP];
#pragma unroll
    for (int j = 0; j < NP; ++j) {
        u64 t01 = fadd2(W[0][j], W[1][j]);
        u64 t23 = fadd2(W[2][j], W[3][j]);
        u64 t45 = fadd2(W[4][j], W[5][j]);
        r[j] = upk(fadd2(fadd2(t01, t23), t45));
    }

    float2 acc = prod6f(r);

#pragma unroll
    for (int t = 1; t < 32; ++t) {
        const int bit = (t & 1) ? 0 : ((t & 2) ? 1 : ((t & 4) ? 2 : ((t & 8) ? 3 : 4)));
        const int a   = bit + 1;                              // flipped row (1..5)
        const bool neg = (((t ^ (t >> 1)) >> bit) & 1) != 0;
        const float s2v = neg ? -2.0f : 2.0f;                 // fp32 immediate

#pragma unroll
        for (int j = 0; j < NP; ++j) {
            float2 w = upk(W[a][j]);
            r[j].x = fmaf(s2v, w.x, r[j].x);
            r[j].y = fmaf(s2v, w.y, r[j].y);
        }
        float2 p = prod6f(r);
        if (t & 1) { acc.x -= p.x; acc.y -= p.y; }            // parity (-1)^t
        else       { acc.x += p.x; acc.y += p.y; }
    }

    const float K = (acc.x * acc.x + acc.y * acc.y) * (1.0f / 1024.0f);
    out[(i0 + li) * N_SAMP + (j0 + lj)] = K;

    // ---------------- self-reset for the next graph replay --------------------
    if (tid == 0) {
        unsigned f = atomicAdd(&g_done, 1u);
        if (f == (unsigned)(NBLK - 1)) {
            g_ticket = 0u;
            g_cnt    = 0u;
            g_done   = 0u;
            __threadfence();
        }
    }
}

// ---------------------------------------------------------------------------
extern "C" void kernel_launch(void* const* d_in, const int* in_sizes, int n_in,
                              void* d_out, int out_size)
{
    const float* x1   = (const float*)d_in[0];
    const float* x2   = (const float*)d_in[1];
    const float* A_re = (const float*)d_in[2];
    const float* A_im = (const float*)d_in[3];
    const float* B_re = (const float*)d_in[4];
    const float* B_im = (const float*)d_in[5];

    dim3 grid(N_SAMP / 16, N_SAMP / 16);   // 24 x 24 = 576 blocks
    fused_kernel<<<grid, 256>>>(x1, x2, A_re, A_im, B_re, B_im, (float*)d_out);
}

// round 15
// speedup vs baseline: 1.6662x; 1.6662x over previous
#include <cuda_runtime.h>

#define N_SAMP 384
#define M 12
#define NP 6
#define UC (M * NP)      // 72 complex entries per sample

typedef unsigned long long u64;

// Duplicated packed operand formats (built once in stage 1), 16B-paired:
// g_u1d entry e=(k*6+b): [2e]=(re,im)=bp  [2e+1]=(-im,re)=bn
// g_u2d entry e=(k*6+a): [2e]=(cre,cre)=aR [2e+1]=(cim,cim)=aI  (c = conj(U2))
__device__ __align__(16) float2 g_u1d[N_SAMP * UC * 2];
__device__ __align__(16) float2 g_u2d[N_SAMP * UC * 2];

__device__ __forceinline__ float2 cmul(float2 a, float2 b) {
    return make_float2(a.x * b.x - a.y * b.y, a.x * b.y + a.y * b.x);
}

// ---- packed f32x2 helpers ----
__device__ __forceinline__ float2 upk(u64 d) {
    float2 r; asm("mov.b64 {%0,%1}, %2;" : "=f"(r.x), "=f"(r.y) : "l"(d)); return r;
}
__device__ __forceinline__ u64 ffma2(u64 a, u64 b, u64 c) {
    u64 d; asm("fma.rn.f32x2 %0, %1, %2, %3;" : "=l"(d) : "l"(a), "l"(b), "l"(c)); return d;
}
__device__ __forceinline__ u64 fmul2(u64 a, u64 b) {
    u64 d; asm("mul.rn.f32x2 %0, %1, %2;" : "=l"(d) : "l"(a), "l"(b)); return d;
}
__device__ __forceinline__ u64 fadd2(u64 a, u64 b) {
    u64 d; asm("add.rn.f32x2 %0, %1, %2;" : "=l"(d) : "l"(a), "l"(b)); return d;
}

// ---------------------------------------------------------------------------
// Stage 1 (single launch, grid=768): U(x) = A @ diag(exp(ix)) @ B, first NP cols,
// written out in duplicated packed formats.
// ---------------------------------------------------------------------------
__global__ void build_u_kernel(const float* __restrict__ x1,
                               const float* __restrict__ x2,
                               const float* __restrict__ A_re,
                               const float* __restrict__ A_im,
                               const float* __restrict__ B_re,
                               const float* __restrict__ B_im)
{
    __shared__ float2 ph[M];
    __shared__ float2 sA[M * M];
    __shared__ float2 sB[M][NP];

    const int s      = blockIdx.x;
    const int tid    = threadIdx.x;
    const int second = (s >= N_SAMP);
    const int ss     = second ? s - N_SAMP : s;
    const float* x   = second ? x2 : x1;

    if (tid < M * M) sA[tid] = make_float2(A_re[tid], A_im[tid]);
    if (tid < M * NP) {
        int b = tid / NP, c = tid - b * NP;
        sB[b][c] = make_float2(B_re[b * M + c], B_im[b * M + c]);
    }
    if (tid < M) {
        float sn, cs;
        sincosf(x[ss * M + tid], &sn, &cs);
        ph[tid] = make_float2(cs, sn);
    }
    __syncthreads();

    if (tid < M * NP) {
        const int a = tid / NP;
        const int c = tid - a * NP;
        float2 acc = make_float2(0.f, 0.f);
#pragma unroll
        for (int b = 0; b < M; ++b) {
            float2 t  = cmul(ph[b], sB[b][c]);
            float2 Av = sA[a * M + b];
            acc.x += Av.x * t.x - Av.y * t.y;
            acc.y += Av.x * t.y + Av.y * t.x;
        }
        const int base = (ss * UC + tid) * 2;
        if (second) {
            g_u2d[base + 0] = make_float2(acc.x, acc.x);     // aR (conj re)
            g_u2d[base + 1] = make_float2(-acc.y, -acc.y);   // aI (conj im)
        } else {
            g_u1d[base + 0] = make_float2(acc.x, acc.y);     // bp
            g_u1d[base + 1] = make_float2(-acc.y, acc.x);    // bn
        }
    }
}

// ---------------------------------------------------------------------------
// Stage 2 (launched with programmatic stream serialization — PDL):
// W[a][b] = sum_k conjU2[j][k][a]*U1[i][k][b]  (FFMA2; 128-bit b-side buffer,
// streamed a-side). Glynn permanent (single Gray chain, FFMA-imm updates).
// 16x16 pairs / 256 threads, 2 blocks/SM.  Byte-identical math to R12 best.
// ---------------------------------------------------------------------------
#define SPV 73   // smem pitch in ulonglong2 (16B units, odd -> conflict-free)

__device__ __forceinline__ float2 prod6f(const float2* r) {
    float2 p01 = cmul(r[0], r[1]);
    float2 p23 = cmul(r[2], r[3]);
    float2 p45 = cmul(r[4], r[5]);
    return cmul(cmul(p01, p23), p45);
}

__global__ __launch_bounds__(256, 2) void pair_kernel(float* __restrict__ out)
{
    __shared__ __align__(16) ulonglong2 s1[16 * SPV];
    __shared__ __align__(16) ulonglong2 s2[16 * SPV];

    const int i0  = blockIdx.y * 16;
    const int j0  = blockIdx.x * 16;
    const int tid = threadIdx.x;

    // PDL: block is resident early; wait for build_u_kernel's stores to flush.
    cudaGridDependencySynchronize();

    const ulonglong2* __restrict__ gu1 = (const ulonglong2*)g_u1d;
    const ulonglong2* __restrict__ gu2 = (const ulonglong2*)g_u2d;
    for (int e = tid; e < 16 * UC; e += 256) {
        int l = e / UC;
        int r = e - l * UC;
        s1[l * SPV + r] = gu1[(i0 + l) * UC + r];
        s2[l * SPV + r] = gu2[(j0 + l) * UC + r];
    }
    __syncthreads();

    const int lj = tid & 15;        // j fastest -> coalesced output
    const int li = tid >> 4;
    const ulonglong2* __restrict__ p1 = &s1[li * SPV];   // {bp, bn}
    const ulonglong2* __restrict__ p2 = &s2[lj * SPV];   // {aR, aI}

    u64 W[NP][NP];

    // k = 0 initializes W
    {
        ulonglong2 bb[NP];
#pragma unroll
        for (int b = 0; b < NP; ++b) bb[b] = p1[b];
#pragma unroll
        for (int a = 0; a < NP; ++a) {
            const ulonglong2 av = p2[a];
#pragma unroll
            for (int b = 0; b < NP; ++b)
                W[a][b] = ffma2(av.y, bb[b].y, fmul2(av.x, bb[b].x));
        }
    }

#pragma unroll
    for (int k = 1; k < M; ++k) {
        ulonglong2 bb[NP];
#pragma unroll
        for (int b = 0; b < NP; ++b) bb[b] = p1[k * NP + b];
#pragma unroll
        for (int a = 0; a < NP; ++a) {
            const ulonglong2 av = p2[k * NP + a];
#pragma unroll
            for (int b = 0; b < NP; ++b) {
                W[a][b] = ffma2(av.x, bb[b].x, W[a][b]);
                W[a][b] = ffma2(av.y, bb[b].y, W[a][b]);
            }
        }
    }

    // --- Glynn permanent, n=6, single Gray chain, FFMA-imm updates ---
    float2 r[NP];
#pragma unroll
    for (int j = 0; j < NP; ++j) {
        u64 t01 = fadd2(W[0][j], W[1][j]);
        u64 t23 = fadd2(W[2][j], W[3][j]);
        u64 t45 = fadd2(W[4][j], W[5][j]);
        r[j] = upk(fadd2(fadd2(t01, t23), t45));
    }

    float2 acc = prod6f(r);

#pragma unroll
    for (int t = 1; t < 32; ++t) {
        const int bit = (t & 1) ? 0 : ((t & 2) ? 1 : ((t & 4) ? 2 : ((t & 8) ? 3 : 4)));
        const int a   = bit + 1;                              // flipped row (1..5)
        const bool neg = (((t ^ (t >> 1)) >> bit) & 1) != 0;
        const float s2v = neg ? -2.0f : 2.0f;                 // fp32 immediate

#pragma unroll
        for (int j = 0; j < NP; ++j) {
            float2 w = upk(W[a][j]);
            r[j].x = fmaf(s2v, w.x, r[j].x);
            r[j].y = fmaf(s2v, w.y, r[j].y);
        }
        float2 p = prod6f(r);
        if (t & 1) { acc.x -= p.x; acc.y -= p.y; }            // parity (-1)^t
        else       { acc.x += p.x; acc.y += p.y; }
    }

    // perm = acc / 32 ; K = |perm|^2 = |acc|^2 / 1024
    const float K = (acc.x * acc.x + acc.y * acc.y) * (1.0f / 1024.0f);
    out[(i0 + li) * N_SAMP + (j0 + lj)] = K;
}

// ---------------------------------------------------------------------------
extern "C" void kernel_launch(void* const* d_in, const int* in_sizes, int n_in,
                              void* d_out, int out_size)
{
    const float* x1   = (const float*)d_in[0];
    const float* x2   = (const float*)d_in[1];
    const float* A_re = (const float*)d_in[2];
    const float* A_im = (const float*)d_in[3];
    const float* B_re = (const float*)d_in[4];
    const float* B_im = (const float*)d_in[5];

    build_u_kernel<<<2 * N_SAMP, 160>>>(x1, x2, A_re, A_im, B_re, B_im);

    // Pair kernel with programmatic dependent launch: overlaps its launch &
    // block residency with the tail of build_u_kernel; the device-side
    // cudaGridDependencySynchronize() provides the ordering.
    cudaLaunchConfig_t cfg = {};
    cfg.gridDim  = dim3(N_SAMP / 16, N_SAMP / 16, 1);   // 24 x 24
    cfg.blockDim = dim3(256, 1, 1);
    cfg.dynamicSmemBytes = 0;
    cfg.stream = 0;   // legacy default stream (same as <<<>>> above)

    cudaLaunchAttribute attrs[1];
    attrs[0].id = cudaLaunchAttributeProgrammaticStreamSerialization;
    attrs[0].val.programmaticStreamSerializationAllowed = 1;
    cfg.attrs = attrs;
    cfg.numAttrs = 1;

    cudaError_t err = cudaLaunchKernelEx(&cfg, pair_kernel, (float*)d_out);
    if (err != cudaSuccess) {
        // Fallback: plain launch (keeps correctness if PDL unsupported here)
        dim3 grid(N_SAMP / 16, N_SAMP / 16);
        pair_kernel<<<grid, 256>>>((float*)d_out);
    }
}

// round 16
// speedup vs baseline: 1.7933x; 1.0763x over previous
#include <cuda_runtime.h>

#define N_SAMP 384
#define M 12
#define NP 6
#define UC (M * NP)      // 72 complex entries per sample

typedef unsigned long long u64;

// Duplicated packed operand formats (built once in stage 1), 16B-paired:
// g_u1d entry e=(k*6+b): [2e]=(re,im)=bp  [2e+1]=(-im,re)=bn
// g_u2d entry e=(k*6+a): [2e]=(cre,cre)=aR [2e+1]=(cim,cim)=aI  (c = conj(U2))
__device__ __align__(16) float2 g_u1d[N_SAMP * UC * 2];
__device__ __align__(16) float2 g_u2d[N_SAMP * UC * 2];

__device__ __forceinline__ float2 cmul(float2 a, float2 b) {
    return make_float2(a.x * b.x - a.y * b.y, a.x * b.y + a.y * b.x);
}

// ---- packed f32x2 helpers ----
__device__ __forceinline__ u64 pk2(float lo, float hi) {
    u64 d; asm("mov.b64 %0, {%1,%2};" : "=l"(d) : "f"(lo), "f"(hi)); return d;
}
__device__ __forceinline__ float2 upk(u64 d) {
    float2 r; asm("mov.b64 {%0,%1}, %2;" : "=f"(r.x), "=f"(r.y) : "l"(d)); return r;
}
__device__ __forceinline__ u64 ffma2(u64 a, u64 b, u64 c) {
    u64 d; asm("fma.rn.f32x2 %0, %1, %2, %3;" : "=l"(d) : "l"(a), "l"(b), "l"(c)); return d;
}
__device__ __forceinline__ u64 fmul2(u64 a, u64 b) {
    u64 d; asm("mul.rn.f32x2 %0, %1, %2;" : "=l"(d) : "l"(a), "l"(b)); return d;
}
__device__ __forceinline__ u64 fadd2(u64 a, u64 b) {
    u64 d; asm("add.rn.f32x2 %0, %1, %2;" : "=l"(d) : "l"(a), "l"(b)); return d;
}

// Packed complex multiply: 1 FMUL2 + 1 FFMA2 on the fma pipe; operand
// swizzles (dup / neg / swap) ride the near-idle ALU pipe.
// z1*z2 = (x1,x1).*(x2,y2) + (-y1,y1).*(y2,x2)
__device__ __forceinline__ u64 cmulp(u64 z1, u64 z2) {
    float2 a = upk(z1), b = upk(z2);
    u64 axx = pk2(a.x, a.x);
    u64 ayn = pk2(-a.y, a.y);
    u64 bsw = pk2(b.y, b.x);
    return ffma2(axx, z2, fmul2(ayn, bsw));
}

// ---------------------------------------------------------------------------
// Stage 1 (single launch, grid=768): U(x) = A @ diag(exp(ix)) @ B, first NP cols,
// written out in duplicated packed formats.
// ---------------------------------------------------------------------------
__global__ void build_u_kernel(const float* __restrict__ x1,
                               const float* __restrict__ x2,
                               const float* __restrict__ A_re,
                               const float* __restrict__ A_im,
                               const float* __restrict__ B_re,
                               const float* __restrict__ B_im)
{
    __shared__ float2 ph[M];
    __shared__ float2 sA[M * M];
    __shared__ float2 sB[M][NP];

    const int s      = blockIdx.x;
    const int tid    = threadIdx.x;
    const int second = (s >= N_SAMP);
    const int ss     = second ? s - N_SAMP : s;
    const float* x   = second ? x2 : x1;

    if (tid < M * M) sA[tid] = make_float2(A_re[tid], A_im[tid]);
    if (tid < M * NP) {
        int b = tid / NP, c = tid - b * NP;
        sB[b][c] = make_float2(B_re[b * M + c], B_im[b * M + c]);
    }
    if (tid < M) {
        float sn, cs;
        sincosf(x[ss * M + tid], &sn, &cs);
        ph[tid] = make_float2(cs, sn);
    }
    __syncthreads();

    if (tid < M * NP) {
        const int a = tid / NP;
        const int c = tid - a * NP;
        float2 acc = make_float2(0.f, 0.f);
#pragma unroll
        for (int b = 0; b < M; ++b) {
            float2 t  = cmul(ph[b], sB[b][c]);
            float2 Av = sA[a * M + b];
            acc.x += Av.x * t.x - Av.y * t.y;
            acc.y += Av.x * t.y + Av.y * t.x;
        }
        const int base = (ss * UC + tid) * 2;
        if (second) {
            g_u2d[base + 0] = make_float2(acc.x, acc.x);     // aR (conj re)
            g_u2d[base + 1] = make_float2(-acc.y, -acc.y);   // aI (conj im)
        } else {
            g_u1d[base + 0] = make_float2(acc.x, acc.y);     // bp
            g_u1d[base + 1] = make_float2(-acc.y, acc.x);    // bn
        }
    }
}

// ---------------------------------------------------------------------------
// Stage 2 (PDL launch): GEMM identical to R12/R15 best; Glynn with packed
// rowsums, FFMA-imm updates, and packed-cmul product tree.
// 16x16 pairs / 256 threads, 2 blocks/SM.
// ---------------------------------------------------------------------------
#define SPV 73   // smem pitch in ulonglong2 (16B units, odd -> conflict-free)

// Product of 6 packed rowsums, balanced tree, packed cmul (2 fma-ops each).
__device__ __forceinline__ u64 prod6p(const u64* r) {
    u64 p01 = cmulp(r[0], r[1]);
    u64 p23 = cmulp(r[2], r[3]);
    u64 p45 = cmulp(r[4], r[5]);
    return cmulp(cmulp(p01, p23), p45);
}

__global__ __launch_bounds__(256, 2) void pair_kernel(float* __restrict__ out)
{
    __shared__ __align__(16) ulonglong2 s1[16 * SPV];
    __shared__ __align__(16) ulonglong2 s2[16 * SPV];

    const int i0  = blockIdx.y * 16;
    const int j0  = blockIdx.x * 16;
    const int tid = threadIdx.x;

    // PDL: block resident early; wait for build_u_kernel's stores to flush.
    cudaGridDependencySynchronize();

    const ulonglong2* __restrict__ gu1 = (const ulonglong2*)g_u1d;
    const ulonglong2* __restrict__ gu2 = (const ulonglong2*)g_u2d;
    for (int e = tid; e < 16 * UC; e += 256) {
        int l = e / UC;
        int r = e - l * UC;
        s1[l * SPV + r] = gu1[(i0 + l) * UC + r];
        s2[l * SPV + r] = gu2[(j0 + l) * UC + r];
    }
    __syncthreads();

    const int lj = tid & 15;        // j fastest -> coalesced output
    const int li = tid >> 4;
    const ulonglong2* __restrict__ p1 = &s1[li * SPV];   // {bp, bn}
    const ulonglong2* __restrict__ p2 = &s2[lj * SPV];   // {aR, aI}

    u64 W[NP][NP];

    // k = 0 initializes W
    {
        ulonglong2 bb[NP];
#pragma unroll
        for (int b = 0; b < NP; ++b) bb[b] = p1[b];
#pragma unroll
        for (int a = 0; a < NP; ++a) {
            const ulonglong2 av = p2[a];
#pragma unroll
            for (int b = 0; b < NP; ++b)
                W[a][b] = ffma2(av.y, bb[b].y, fmul2(av.x, bb[b].x));
        }
    }

#pragma unroll
    for (int k = 1; k < M; ++k) {
        ulonglong2 bb[NP];
#pragma unroll
        for (int b = 0; b < NP; ++b) bb[b] = p1[k * NP + b];
#pragma unroll
        for (int a = 0; a < NP; ++a) {
            const ulonglong2 av = p2[k * NP + a];
#pragma unroll
            for (int b = 0; b < NP; ++b) {
                W[a][b] = ffma2(av.x, bb[b].x, W[a][b]);
                W[a][b] = ffma2(av.y, bb[b].y, W[a][b]);
            }
        }
    }

    // --- Glynn permanent, n=6, single Gray chain ---
    // Rowsums packed; updates scalar FFMA-imm (rt=1); product tree packed.
    u64 r[NP];
#pragma unroll
    for (int j = 0; j < NP; ++j) {
        u64 t01 = fadd2(W[0][j], W[1][j]);
        u64 t23 = fadd2(W[2][j], W[3][j]);
        u64 t45 = fadd2(W[4][j], W[5][j]);
        r[j] = fadd2(fadd2(t01, t23), t45);
    }

    float2 acc = upk(prod6p(r));

#pragma unroll
    for (int t = 1; t < 32; ++t) {
        const int bit = (t & 1) ? 0 : ((t & 2) ? 1 : ((t & 4) ? 2 : ((t & 8) ? 3 : 4)));
        const int a   = bit + 1;                              // flipped row (1..5)
        const bool neg = (((t ^ (t >> 1)) >> bit) & 1) != 0;
        const float s2v = neg ? -2.0f : 2.0f;                 // fp32 immediate

#pragma unroll
        for (int j = 0; j < NP; ++j) {
            float2 rv = upk(r[j]);
            float2 w  = upk(W[a][j]);
            rv.x = fmaf(s2v, w.x, rv.x);                      // FFMA-imm, rt=1
            rv.y = fmaf(s2v, w.y, rv.y);
            r[j] = pk2(rv.x, rv.y);
        }
        float2 p = upk(prod6p(r));
        if (t & 1) { acc.x -= p.x; acc.y -= p.y; }            // parity (-1)^t
        else       { acc.x += p.x; acc.y += p.y; }
    }

    // perm = acc / 32 ; K = |perm|^2 = |acc|^2 / 1024
    const float K = (acc.x * acc.x + acc.y * acc.y) * (1.0f / 1024.0f);
    out[(i0 + li) * N_SAMP + (j0 + lj)] = K;
}

// ---------------------------------------------------------------------------
extern "C" void kernel_launch(void* const* d_in, const int* in_sizes, int n_in,
                              void* d_out, int out_size)
{
    const float* x1   = (const float*)d_in[0];
    const float* x2   = (const float*)d_in[1];
    const float* A_re = (const float*)d_in[2];
    const float* A_im = (const float*)d_in[3];
    const float* B_re = (const float*)d_in[4];
    const float* B_im = (const float*)d_in[5];

    build_u_kernel<<<2 * N_SAMP, 160>>>(x1, x2, A_re, A_im, B_re, B_im);

    // Pair kernel with programmatic dependent launch (overlap launch latency).
    cudaLaunchConfig_t cfg = {};
    cfg.gridDim  = dim3(N_SAMP / 16, N_SAMP / 16, 1);   // 24 x 24
    cfg.blockDim = dim3(256, 1, 1);
    cfg.dynamicSmemBytes = 0;
    cfg.stream = 0;

    cudaLaunchAttribute attrs[1];
    attrs[0].id = cudaLaunchAttributeProgrammaticStreamSerialization;
    attrs[0].val.programmaticStreamSerializationAllowed = 1;
    cfg.attrs = attrs;
    cfg.numAttrs = 1;

    cudaError_t err = cudaLaunchKernelEx(&cfg, pair_kernel, (float*)d_out);
    if (err != cudaSuccess) {
        dim3 grid(N_SAMP / 16, N_SAMP / 16);
        pair_kernel<<<grid, 256>>>((float*)d_out);
    }
}